// round 2
// baseline (speedup 1.0000x reference)
#include <cuda_runtime.h>

#define NB  64
#define CCH 3
#define HH  256
#define WW  256
#define DD  512

struct BParam { float m00, m01, m02, m10, m11, m12, w1, lev; int l0; };

__device__ BParam g_bp[NB];
__device__ __align__(16) float g_pyr1[NB * CCH * 128 * 128];
__device__ __align__(16) float g_pyr2[NB * CCH * 64 * 64];
__device__ __align__(16) float g_pyr3[NB * CCH * 32 * 32];

// ---------------------------------------------------------------------------
// Kernel 1: linear head + affine params. One block per batch, 4 warps.
// ---------------------------------------------------------------------------
__global__ void params_kernel(const float* __restrict__ feat,
                              const float* __restrict__ lw,
                              const float* __restrict__ lb,
                              float* __restrict__ out_mat,
                              float* __restrict__ out_aff) {
    int n = blockIdx.x;
    int warp = threadIdx.x >> 5, lane = threadIdx.x & 31;
    const float* f  = feat + n * DD;
    const float* wr = lw + warp * DD;
    float s = 0.f;
    #pragma unroll 4
    for (int k = lane; k < DD; k += 32) s += f[k] * wr[k];
    #pragma unroll
    for (int o = 16; o; o >>= 1) s += __shfl_xor_sync(0xffffffffu, s, o);
    __shared__ float p[4];
    if (lane == 0) p[warp] = s + lb[warp];
    __syncthreads();
    if (threadIdx.x == 0) {
        float rot = tanhf(p[0]) * 3.14159265358979323846f;
        float sc  = expf(p[1]);
        float sx  = p[2], sy = p[3];
        float cs = cosf(rot), sn = sinf(rot);
        float m00 = sc * cs, m01 = -sc * sn, m10 = sc * sn, m11 = sc * cs;
        float* mo = out_mat + n * 6;
        mo[0] = m00; mo[1] = m01; mo[2] = sx;
        mo[3] = m10; mo[4] = m11; mo[5] = sy;
        float* ao = out_aff + n * 4;
        ao[0] = rot; ao[1] = sc; ao[2] = sx; ao[3] = sy;
        // Affine warp: per-pixel jacobian is constant; with H==W both column
        // norms equal exactly sc. levels = clip(log2(max(sc,1)), 0, 2.5)
        float level = log2f(fmaxf(sc, 1.f));
        level = fminf(fmaxf(level, 0.f), 2.5f);
        int l0 = (int)level;
        if (l0 > 2) l0 = 2;
        BParam bp;
        bp.m00 = m00; bp.m01 = m01; bp.m02 = sx;
        bp.m10 = m10; bp.m11 = m11; bp.m12 = sy;
        bp.w1 = level - (float)l0; bp.l0 = l0; bp.lev = level;
        g_bp[n] = bp;
    }
}

// ---------------------------------------------------------------------------
// Kernel 2: img -> pyr1 (256 -> 128). 2 outputs per thread, per-batch skip.
// reflect pad (1,2), 4x4 stride-2 separable [1,3,3,1]/8.
// ---------------------------------------------------------------------------
__global__ void down0_kernel(const float* __restrict__ img) {
    constexpr int Hi = 256, Wi = 256, Ho = 128, Wo = 128;
    constexpr int PAIRS = Wo / 2;                       // 64
    constexpr int total = NB * CCH * Ho * PAIRS;

    int idx = blockIdx.x * blockDim.x + threadIdx.x;
    if (idx >= total) return;
    int owp = idx & (PAIRS - 1);
    int t   = idx >> 6;
    int oh  = t & (Ho - 1);
    int nc  = t >> 7;
    int n   = nc / CCH;
    if (g_bp[n].lev <= 0.f) return;                     // pyramid unused

    const float* src = img + (size_t)nc * Hi * Wi;
    const float kk[4] = {0.125f, 0.375f, 0.375f, 0.125f};
    int ow0 = owp * 2;

    int rr[4], cc[6];
    #pragma unroll
    for (int i = 0; i < 4; i++) {
        int r = 2 * oh - 1 + i;
        r = r < 0 ? -r : r;
        r = r >= Hi ? 2 * Hi - 2 - r : r;
        rr[i] = r * Wi;
    }
    #pragma unroll
    for (int i = 0; i < 6; i++) {
        int c = 2 * ow0 - 1 + i;
        c = c < 0 ? -c : c;
        c = c >= Wi ? 2 * Wi - 2 - c : c;
        cc[i] = c;
    }
    float a0 = 0.f, a1 = 0.f;
    #pragma unroll
    for (int i = 0; i < 4; i++) {
        float v0 = __ldg(src + rr[i] + cc[0]);
        float v1 = __ldg(src + rr[i] + cc[1]);
        float v2 = __ldg(src + rr[i] + cc[2]);
        float v3 = __ldg(src + rr[i] + cc[3]);
        float v4 = __ldg(src + rr[i] + cc[4]);
        float v5 = __ldg(src + rr[i] + cc[5]);
        float r0 = kk[0]*v0 + kk[1]*v1 + kk[2]*v2 + kk[3]*v3;
        float r1 = kk[0]*v2 + kk[1]*v3 + kk[2]*v4 + kk[3]*v5;
        a0 += kk[i] * r0;
        a1 += kk[i] * r1;
    }
    float2* dst = reinterpret_cast<float2*>(g_pyr1 + (size_t)nc * Ho * Wo + oh * Wo + ow0);
    *dst = make_float2(a0, a1);
}

// ---------------------------------------------------------------------------
// Kernel 3: pyr1 -> pyr2 -> pyr3 fused. One block per (n,c) plane.
// pyr2 (64x64) staged in smem, pyr3 (32x32) computed from smem.
// ---------------------------------------------------------------------------
__global__ void down12_kernel() {
    int nc = blockIdx.x;
    int n  = nc / CCH;
    float lev = g_bp[n].lev;
    if (lev <= 1.f) return;                             // pyr2/pyr3 unused

    __shared__ float s2[64 * 64];
    const float kk[4] = {0.125f, 0.375f, 0.375f, 0.125f};

    // Phase A: pyr1(128x128) -> pyr2(64x64)
    {
        const float* src = g_pyr1 + (size_t)nc * 128 * 128;
        float* dst = g_pyr2 + (size_t)nc * 64 * 64;
        for (int p = threadIdx.x; p < 64 * 64; p += blockDim.x) {
            int oh = p >> 6, ow = p & 63;
            float acc = 0.f;
            #pragma unroll
            for (int i = 0; i < 4; i++) {
                int r = 2 * oh - 1 + i;
                r = r < 0 ? -r : r;
                r = r >= 128 ? 254 - r : r;
                const float* row = src + r * 128;
                float rv = 0.f;
                #pragma unroll
                for (int j = 0; j < 4; j++) {
                    int c = 2 * ow - 1 + j;
                    c = c < 0 ? -c : c;
                    c = c >= 128 ? 254 - c : c;
                    rv += kk[j] * __ldg(row + c);
                }
                acc += kk[i] * rv;
            }
            s2[p] = acc;
            dst[p] = acc;
        }
    }
    if (lev <= 2.f) return;                             // pyr3 unused
    __syncthreads();

    // Phase B: pyr2(smem 64x64) -> pyr3(32x32)
    {
        float* dst = g_pyr3 + (size_t)nc * 32 * 32;
        for (int p = threadIdx.x; p < 32 * 32; p += blockDim.x) {
            int oh = p >> 5, ow = p & 31;
            float acc = 0.f;
            #pragma unroll
            for (int i = 0; i < 4; i++) {
                int r = 2 * oh - 1 + i;
                r = r < 0 ? -r : r;
                r = r >= 64 ? 126 - r : r;
                const float* row = s2 + r * 64;
                float rv = 0.f;
                #pragma unroll
                for (int j = 0; j < 4; j++) {
                    int c = 2 * ow - 1 + j;
                    c = c < 0 ? -c : c;
                    c = c >= 64 ? 126 - c : c;
                    rv += kk[j] * row[c];
                }
                acc += kk[i] * rv;
            }
            dst[p] = acc;
        }
    }
}

// ---------------------------------------------------------------------------
// Bilinear sample w/ border clamp, accumulate 3 channels scaled by wgt.
// ---------------------------------------------------------------------------
__device__ __forceinline__ void sample_lvl(const float* __restrict__ base, int S,
                                           float gx, float gy, float wgt,
                                           float* acc) {
    float x = fmaf(gx + 1.f, 0.5f * (float)S, -0.5f);
    float y = fmaf(gy + 1.f, 0.5f * (float)S, -0.5f);
    float xf = floorf(x), yf = floorf(y);
    float tx = x - xf, ty = y - yf;
    int x0 = (int)xf, y0 = (int)yf;
    int x0c = min(max(x0, 0), S - 1);
    int x1c = min(max(x0 + 1, 0), S - 1);
    int y0c = min(max(y0, 0), S - 1);
    int y1c = min(max(y0 + 1, 0), S - 1);
    float w00 = (1.f - tx) * (1.f - ty) * wgt;
    float w01 = tx * (1.f - ty) * wgt;
    float w10 = (1.f - tx) * ty * wgt;
    float w11 = tx * ty * wgt;
    int r0 = y0c * S, r1 = y1c * S;
    int plane = S * S;
    #pragma unroll
    for (int c = 0; c < 3; c++) {
        const float* p = base + c * plane;
        acc[c] += __ldg(p + r0 + x0c) * w00 + __ldg(p + r0 + x1c) * w01
                + __ldg(p + r1 + x0c) * w10 + __ldg(p + r1 + x1c) * w11;
    }
}

// ---------------------------------------------------------------------------
// Kernel 4: grid gen + mipmap warp. 4 pixels per thread, streaming stores.
// ---------------------------------------------------------------------------
__global__ void warp_kernel(const float* __restrict__ img,
                            float* __restrict__ out,
                            float* __restrict__ grid_out) {
    int n = blockIdx.z;
    int w0 = (blockIdx.x * 32 + threadIdx.x) * 4;
    int h  = blockIdx.y * 4 + threadIdx.y;

    BParam bp = g_bp[n];

    float hc = ((float)h + 0.5f) * (2.f / (float)HH) - 1.f;
    float wc = ((float)w0 + 0.5f) * (2.f / (float)WW) - 1.f;
    float dgx = bp.m00 * (2.f / (float)WW);
    float dgy = bp.m10 * (2.f / (float)WW);
    float gx0 = bp.m00 * wc + bp.m01 * hc + bp.m02;
    float gy0 = bp.m10 * wc + bp.m11 * hc + bp.m12;

    float gx[4], gy[4];
    gx[0] = gx0;           gy[0] = gy0;
    gx[1] = gx0 + dgx;     gy[1] = gy0 + dgy;
    gx[2] = gx0 + 2*dgx;   gy[2] = gy0 + 2*dgy;
    gx[3] = gx0 + 3*dgx;   gy[3] = gy0 + 3*dgy;

    // grid store: [n][h][w][2] as two float4 (evict-first: write-once data)
    {
        float* gp = grid_out + ((size_t)n * HH * WW + (size_t)h * WW + w0) * 2;
        __stcs(reinterpret_cast<float4*>(gp),     make_float4(gx[0], gy[0], gx[1], gy[1]));
        __stcs(reinterpret_cast<float4*>(gp + 4), make_float4(gx[2], gy[2], gx[3], gy[3]));
    }

    int l0 = bp.l0;
    float w1 = bp.w1;
    float wgt0 = 1.f - w1;

    const float* b0; int s0;
    if (l0 == 0)      { b0 = img    + (size_t)n * CCH * 256 * 256; s0 = 256; }
    else if (l0 == 1) { b0 = g_pyr1 + (size_t)n * CCH * 128 * 128; s0 = 128; }
    else              { b0 = g_pyr2 + (size_t)n * CCH * 64 * 64;   s0 = 64;  }

    const float* b1 = nullptr; int s1 = 0;
    if (w1 > 0.f) {
        if (l0 == 0)      { b1 = g_pyr1 + (size_t)n * CCH * 128 * 128; s1 = 128; }
        else if (l0 == 1) { b1 = g_pyr2 + (size_t)n * CCH * 64 * 64;   s1 = 64;  }
        else              { b1 = g_pyr3 + (size_t)n * CCH * 32 * 32;   s1 = 32;  }
    }

    float acc[4][3];
    #pragma unroll
    for (int i = 0; i < 4; i++) {
        acc[i][0] = acc[i][1] = acc[i][2] = 0.f;
        sample_lvl(b0, s0, gx[i], gy[i], wgt0, acc[i]);
        if (b1) sample_lvl(b1, s1, gx[i], gy[i], w1, acc[i]);
    }

    float* o = out + (size_t)n * CCH * HH * WW + (size_t)h * WW + w0;
    #pragma unroll
    for (int c = 0; c < 3; c++) {
        __stcs(reinterpret_cast<float4*>(o + (size_t)c * HH * WW),
               make_float4(acc[0][c], acc[1][c], acc[2][c], acc[3][c]));
    }
}

// ---------------------------------------------------------------------------
extern "C" void kernel_launch(void* const* d_in, const int* in_sizes, int n_in,
                              void* d_out, int out_size) {
    const float* img  = (const float*)d_in[0];
    const float* feat = (const float*)d_in[1];
    const float* lw   = (const float*)d_in[2];
    const float* lb   = (const float*)d_in[3];

    float* base   = (float*)d_out;
    float* out_p  = base;                                   // N*C*H*W
    float* grid_p = base + (size_t)NB * CCH * HH * WW;      // +12582912
    float* mat_p  = grid_p + (size_t)NB * HH * WW * 2;      // +8388608
    float* aff_p  = mat_p + NB * 6;

    params_kernel<<<NB, 128>>>(feat, lw, lb, mat_p, aff_p);

    {
        int total0 = NB * CCH * 128 * 64;                   // 2 outputs/thread
        down0_kernel<<<(total0 + 255) / 256, 256>>>(img);
        down12_kernel<<<NB * CCH, 256>>>();
    }

    dim3 blk(32, 4);
    dim3 grd(WW / (32 * 4), HH / 4, NB);
    warp_kernel<<<grd, blk>>>(img, out_p, grid_p);
}

// round 3
// speedup vs baseline: 1.2466x; 1.2466x over previous
#include <cuda_runtime.h>

#define NB  64
#define CCH 3
#define HH  256
#define WW  256
#define DD  512

struct BParam { float m00, m01, m02, m10, m11, m12, w1, lev; int l0; };

__device__ BParam g_bp[NB];
// HWC4 (channels interleaved, 4th lane zero) pyramid + transposed image.
__device__ float4 g_img4[NB * 256 * 256];
__device__ float4 g_pyr14[NB * 128 * 128];
__device__ float4 g_pyr24[NB * 64 * 64];
__device__ float4 g_pyr34[NB * 32 * 32];

// ---------------------------------------------------------------------------
// Kernel 1: linear head + affine params. One block per batch, 4 warps.
// ---------------------------------------------------------------------------
__global__ void params_kernel(const float* __restrict__ feat,
                              const float* __restrict__ lw,
                              const float* __restrict__ lb,
                              float* __restrict__ out_mat,
                              float* __restrict__ out_aff) {
    int n = blockIdx.x;
    int warp = threadIdx.x >> 5, lane = threadIdx.x & 31;
    const float* f  = feat + n * DD;
    const float* wr = lw + warp * DD;
    float s = 0.f;
    #pragma unroll 4
    for (int k = lane; k < DD; k += 32) s += f[k] * wr[k];
    #pragma unroll
    for (int o = 16; o; o >>= 1) s += __shfl_xor_sync(0xffffffffu, s, o);
    __shared__ float p[4];
    if (lane == 0) p[warp] = s + lb[warp];
    __syncthreads();
    if (threadIdx.x == 0) {
        float rot = tanhf(p[0]) * 3.14159265358979323846f;
        float sc  = expf(p[1]);
        float sx  = p[2], sy = p[3];
        float cs = cosf(rot), sn = sinf(rot);
        float m00 = sc * cs, m01 = -sc * sn, m10 = sc * sn, m11 = sc * cs;
        float* mo = out_mat + n * 6;
        mo[0] = m00; mo[1] = m01; mo[2] = sx;
        mo[3] = m10; mo[4] = m11; mo[5] = sy;
        float* ao = out_aff + n * 4;
        ao[0] = rot; ao[1] = sc; ao[2] = sx; ao[3] = sy;
        // Affine warp: jacobian constant per batch; H==W -> both column norms
        // equal exactly sc. levels = clip(log2(max(sc,1)), 0, 2.5)
        float level = log2f(fmaxf(sc, 1.f));
        level = fminf(fmaxf(level, 0.f), 2.5f);
        int l0 = (int)level;
        if (l0 > 2) l0 = 2;
        BParam bp;
        bp.m00 = m00; bp.m01 = m01; bp.m02 = sx;
        bp.m10 = m10; bp.m11 = m11; bp.m12 = sy;
        bp.w1 = level - (float)l0; bp.l0 = l0; bp.lev = level;
        g_bp[n] = bp;
    }
}

// ---------------------------------------------------------------------------
// Kernel 2: CHW -> HWC4 transpose of img. Fully coalesced both sides.
// ---------------------------------------------------------------------------
__global__ void hwc_kernel(const float* __restrict__ img) {
    int idx = blockIdx.x * blockDim.x + threadIdx.x;   // n*65536 + h*256 + w
    int n = idx >> 16;
    int hw = idx & 65535;
    const float* p = img + (size_t)n * 3 * 65536 + hw;
    float4 v;
    v.x = __ldg(p);
    v.y = __ldg(p + 65536);
    v.z = __ldg(p + 131072);
    v.w = 0.f;
    g_img4[idx] = v;
}

// ---------------------------------------------------------------------------
// Kernel 3: img4 -> pyr1 (256->128), HWC4. Per-batch skip.
// reflect pad (1,2), 4x4 stride-2 separable [1,3,3,1]/8.
// ---------------------------------------------------------------------------
__global__ void down0_kernel() {
    int idx = blockIdx.x * blockDim.x + threadIdx.x;   // n*16384 + oh*128 + ow
    int ow = idx & 127;
    int oh = (idx >> 7) & 127;
    int n  = idx >> 14;
    if (g_bp[n].lev <= 0.f) return;

    const float4* src = g_img4 + (size_t)n * 65536;
    const float kk[4] = {0.125f, 0.375f, 0.375f, 0.125f};
    int rr[4], cc[4];
    #pragma unroll
    for (int i = 0; i < 4; i++) {
        int r = 2 * oh - 1 + i;
        r = r < 0 ? -r : r;
        r = r >= 256 ? 510 - r : r;
        rr[i] = r << 8;
        int c = 2 * ow - 1 + i;
        c = c < 0 ? -c : c;
        c = c >= 256 ? 510 - c : c;
        cc[i] = c;
    }
    float4 acc = make_float4(0.f, 0.f, 0.f, 0.f);
    #pragma unroll
    for (int i = 0; i < 4; i++) {
        #pragma unroll
        for (int j = 0; j < 4; j++) {
            float wij = kk[i] * kk[j];
            float4 v = __ldg(src + rr[i] + cc[j]);
            acc.x += wij * v.x; acc.y += wij * v.y; acc.z += wij * v.z;
        }
    }
    g_pyr14[idx] = acc;
}

// ---------------------------------------------------------------------------
// Kernel 4: pyr1 -> pyr2 -> pyr3, fused. One block per batch (uniform skip).
// Phase B reads phase-A output from global (block-local, L2 hit).
// ---------------------------------------------------------------------------
__global__ void down12_kernel() {
    int n = blockIdx.x;
    float lev = g_bp[n].lev;
    if (lev <= 1.f) return;

    const float kk[4] = {0.125f, 0.375f, 0.375f, 0.125f};

    // Phase A: pyr1(128x128) -> pyr2(64x64)
    {
        const float4* src = g_pyr14 + (size_t)n * 16384;
        float4* dst = g_pyr24 + (size_t)n * 4096;
        for (int p = threadIdx.x; p < 4096; p += blockDim.x) {
            int oh = p >> 6, ow = p & 63;
            float4 acc = make_float4(0.f, 0.f, 0.f, 0.f);
            #pragma unroll
            for (int i = 0; i < 4; i++) {
                int r = 2 * oh - 1 + i;
                r = r < 0 ? -r : r;
                r = r >= 128 ? 254 - r : r;
                const float4* row = src + (r << 7);
                #pragma unroll
                for (int j = 0; j < 4; j++) {
                    int c = 2 * ow - 1 + j;
                    c = c < 0 ? -c : c;
                    c = c >= 128 ? 254 - c : c;
                    float w = kk[i] * kk[j];
                    float4 v = __ldg(row + c);
                    acc.x += w * v.x; acc.y += w * v.y; acc.z += w * v.z;
                }
            }
            dst[p] = acc;
        }
    }
    if (lev <= 2.f) return;                 // uniform across block
    __syncthreads();

    // Phase B: pyr2(64x64) -> pyr3(32x32)
    {
        const float4* src = g_pyr24 + (size_t)n * 4096;
        float4* dst = g_pyr34 + (size_t)n * 1024;
        for (int p = threadIdx.x; p < 1024; p += blockDim.x) {
            int oh = p >> 5, ow = p & 31;
            float4 acc = make_float4(0.f, 0.f, 0.f, 0.f);
            #pragma unroll
            for (int i = 0; i < 4; i++) {
                int r = 2 * oh - 1 + i;
                r = r < 0 ? -r : r;
                r = r >= 64 ? 126 - r : r;
                const float4* row = src + (r << 6);
                #pragma unroll
                for (int j = 0; j < 4; j++) {
                    int c = 2 * ow - 1 + j;
                    c = c < 0 ? -c : c;
                    c = c >= 64 ? 126 - c : c;
                    float w = kk[i] * kk[j];
                    float4 v = row[c];
                    acc.x += w * v.x; acc.y += w * v.y; acc.z += w * v.z;
                }
            }
            dst[p] = acc;
        }
    }
}

// ---------------------------------------------------------------------------
// Bilinear sample (border clamp) from an HWC4 plane. One float4 per tap.
// ---------------------------------------------------------------------------
__device__ __forceinline__ void sample4(const float4* __restrict__ base, int S,
                                        float gx, float gy, float wgt,
                                        float* acc) {
    float x = fmaf(gx + 1.f, 0.5f * (float)S, -0.5f);
    float y = fmaf(gy + 1.f, 0.5f * (float)S, -0.5f);
    float xf = floorf(x), yf = floorf(y);
    float tx = x - xf, ty = y - yf;
    int x0 = (int)xf, y0 = (int)yf;
    int x0c = min(max(x0, 0), S - 1);
    int x1c = min(max(x0 + 1, 0), S - 1);
    int y0c = min(max(y0, 0), S - 1);
    int y1c = min(max(y0 + 1, 0), S - 1);
    float w00 = (1.f - tx) * (1.f - ty) * wgt;
    float w01 = tx * (1.f - ty) * wgt;
    float w10 = (1.f - tx) * ty * wgt;
    float w11 = tx * ty * wgt;
    const float4* r0 = base + y0c * S;
    const float4* r1 = base + y1c * S;
    float4 v00 = __ldg(r0 + x0c);
    float4 v01 = __ldg(r0 + x1c);
    float4 v10 = __ldg(r1 + x0c);
    float4 v11 = __ldg(r1 + x1c);
    acc[0] += v00.x * w00 + v01.x * w01 + v10.x * w10 + v11.x * w11;
    acc[1] += v00.y * w00 + v01.y * w01 + v10.y * w10 + v11.y * w11;
    acc[2] += v00.z * w00 + v01.z * w01 + v10.z * w10 + v11.z * w11;
}

// ---------------------------------------------------------------------------
// Kernel 5: grid gen + mipmap warp. Warp covers an 8x8 pixel tile
// (blockDim 8x16, 2 px per thread vertically) to keep rotated gather
// footprints compact in L1.
// ---------------------------------------------------------------------------
__global__ void warp_kernel(float* __restrict__ out,
                            float* __restrict__ grid_out) {
    int n  = blockIdx.z;
    int w  = blockIdx.x * 8 + threadIdx.x;
    int h0 = blockIdx.y * 32 + threadIdx.y * 2;

    BParam bp = g_bp[n];

    float wc  = ((float)w + 0.5f) * (2.f / (float)WW) - 1.f;
    float hc0 = ((float)h0 + 0.5f) * (2.f / (float)HH) - 1.f;
    float dgx = bp.m01 * (2.f / (float)HH);          // per +1 in h
    float dgy = bp.m11 * (2.f / (float)HH);
    float gx0 = bp.m00 * wc + bp.m01 * hc0 + bp.m02;
    float gy0 = bp.m10 * wc + bp.m11 * hc0 + bp.m12;
    float gx1 = gx0 + dgx;
    float gy1 = gy0 + dgy;

    {   // grid stores: [n][h][w][2], 8B aligned float2, evict-first
        float* gp = grid_out + ((size_t)n * 65536 + (size_t)h0 * 256 + w) * 2;
        __stcs(reinterpret_cast<float2*>(gp),       make_float2(gx0, gy0));
        __stcs(reinterpret_cast<float2*>(gp + 512), make_float2(gx1, gy1));
    }

    int l0 = bp.l0;
    float w1 = bp.w1;
    float wgt0 = 1.f - w1;

    const float4* b0; int s0;
    if (l0 == 0)      { b0 = g_img4  + (size_t)n * 65536; s0 = 256; }
    else if (l0 == 1) { b0 = g_pyr14 + (size_t)n * 16384; s0 = 128; }
    else              { b0 = g_pyr24 + (size_t)n * 4096;  s0 = 64;  }

    const float4* b1 = nullptr; int s1 = 0;
    if (w1 > 0.f) {
        if (l0 == 0)      { b1 = g_pyr14 + (size_t)n * 16384; s1 = 128; }
        else if (l0 == 1) { b1 = g_pyr24 + (size_t)n * 4096;  s1 = 64;  }
        else              { b1 = g_pyr34 + (size_t)n * 1024;  s1 = 32;  }
    }

    float a0[3] = {0.f, 0.f, 0.f};
    float a1[3] = {0.f, 0.f, 0.f};
    sample4(b0, s0, gx0, gy0, wgt0, a0);
    sample4(b0, s0, gx1, gy1, wgt0, a1);
    if (b1) {
        sample4(b1, s1, gx0, gy0, w1, a0);
        sample4(b1, s1, gx1, gy1, w1, a1);
    }

    float* o = out + (size_t)n * 3 * 65536 + (size_t)h0 * 256 + w;
    __stcs(o,              a0[0]);
    __stcs(o + 65536,      a0[1]);
    __stcs(o + 131072,     a0[2]);
    __stcs(o + 256,        a1[0]);
    __stcs(o + 65536+256,  a1[1]);
    __stcs(o + 131072+256, a1[2]);
}

// ---------------------------------------------------------------------------
extern "C" void kernel_launch(void* const* d_in, const int* in_sizes, int n_in,
                              void* d_out, int out_size) {
    const float* img  = (const float*)d_in[0];
    const float* feat = (const float*)d_in[1];
    const float* lw   = (const float*)d_in[2];
    const float* lb   = (const float*)d_in[3];

    float* base   = (float*)d_out;
    float* out_p  = base;                                   // N*C*H*W
    float* grid_p = base + (size_t)NB * CCH * HH * WW;
    float* mat_p  = grid_p + (size_t)NB * HH * WW * 2;
    float* aff_p  = mat_p + NB * 6;

    params_kernel<<<NB, 128>>>(feat, lw, lb, mat_p, aff_p);
    hwc_kernel<<<NB * 65536 / 256, 256>>>(img);
    down0_kernel<<<NB * 16384 / 256, 256>>>();
    down12_kernel<<<NB, 256>>>();

    dim3 blk(8, 16);
    dim3 grd(WW / 8, HH / 32, NB);
    warp_kernel<<<grd, blk>>>(out_p, grid_p);
}

// round 4
// speedup vs baseline: 1.4703x; 1.1794x over previous
#include <cuda_runtime.h>

#define NB  64
#define CCH 3
#define HH  256
#define WW  256
#define DD  512

struct BParam { float m00, m01, m02, m10, m11, m12, w1, lev; int l0; };

__device__ BParam g_bp[NB];
// HWC4 (channels interleaved, 4th lane zero) image + pyramid.
__device__ float4 g_img4[NB * 256 * 256];
__device__ float4 g_pyr14[NB * 128 * 128];
__device__ float4 g_pyr24[NB * 64 * 64];
__device__ float4 g_pyr34[NB * 32 * 32];

// ---------------------------------------------------------------------------
// Kernel 1: linear head + affine params. One block per batch, 4 warps.
// ---------------------------------------------------------------------------
__global__ void params_kernel(const float* __restrict__ feat,
                              const float* __restrict__ lw,
                              const float* __restrict__ lb,
                              float* __restrict__ out_mat,
                              float* __restrict__ out_aff) {
    int n = blockIdx.x;
    int warp = threadIdx.x >> 5, lane = threadIdx.x & 31;
    const float* f  = feat + n * DD;
    const float* wr = lw + warp * DD;
    float s = 0.f;
    #pragma unroll 4
    for (int k = lane; k < DD; k += 32) s += f[k] * wr[k];
    #pragma unroll
    for (int o = 16; o; o >>= 1) s += __shfl_xor_sync(0xffffffffu, s, o);
    __shared__ float p[4];
    if (lane == 0) p[warp] = s + lb[warp];
    __syncthreads();
    if (threadIdx.x == 0) {
        float rot = tanhf(p[0]) * 3.14159265358979323846f;
        float sc  = expf(p[1]);
        float sx  = p[2], sy = p[3];
        float cs = cosf(rot), sn = sinf(rot);
        float m00 = sc * cs, m01 = -sc * sn, m10 = sc * sn, m11 = sc * cs;
        float* mo = out_mat + n * 6;
        mo[0] = m00; mo[1] = m01; mo[2] = sx;
        mo[3] = m10; mo[4] = m11; mo[5] = sy;
        float* ao = out_aff + n * 4;
        ao[0] = rot; ao[1] = sc; ao[2] = sx; ao[3] = sy;
        // Affine warp: jacobian constant per batch; H==W -> both column norms
        // equal exactly sc. levels = clip(log2(max(sc,1)), 0, 2.5)
        float level = log2f(fmaxf(sc, 1.f));
        level = fminf(fmaxf(level, 0.f), 2.5f);
        int l0 = (int)level;
        if (l0 > 2) l0 = 2;
        BParam bp;
        bp.m00 = m00; bp.m01 = m01; bp.m02 = sx;
        bp.m10 = m10; bp.m11 = m11; bp.m12 = sy;
        bp.w1 = level - (float)l0; bp.l0 = l0; bp.lev = level;
        g_bp[n] = bp;
    }
}

// ---------------------------------------------------------------------------
// Kernel 2: CHW -> HWC4 transpose of img. 2 pixels/thread, coalesced.
// ---------------------------------------------------------------------------
__global__ void hwc_kernel(const float* __restrict__ img) {
    int t = blockIdx.x * blockDim.x + threadIdx.x;     // over NB*65536/2
    int idx = t * 2;                                   // n*65536 + h*256 + w
    int n = idx >> 16;
    int hw = idx & 65535;
    const float* p = img + (size_t)n * 3 * 65536 + hw;
    float2 r = *reinterpret_cast<const float2*>(p);
    float2 g = *reinterpret_cast<const float2*>(p + 65536);
    float2 b = *reinterpret_cast<const float2*>(p + 131072);
    g_img4[idx]     = make_float4(r.x, g.x, b.x, 0.f);
    g_img4[idx + 1] = make_float4(r.y, g.y, b.y, 0.f);
}

// ---------------------------------------------------------------------------
// Downsample tap helper: reflect pad (1,2), 4x4 stride-2 separable
// [1,3,3,1]/8, HWC4 in/out.
// ---------------------------------------------------------------------------
template <int Si>
__device__ __forceinline__ float4 down_tap(const float4* __restrict__ src,
                                           int oh, int ow) {
    const float kk[4] = {0.125f, 0.375f, 0.375f, 0.125f};
    int rr[4], cc[4];
    #pragma unroll
    for (int i = 0; i < 4; i++) {
        int r = 2 * oh - 1 + i;
        r = r < 0 ? -r : r;
        r = r >= Si ? 2 * Si - 2 - r : r;
        rr[i] = r * Si;
        int c = 2 * ow - 1 + i;
        c = c < 0 ? -c : c;
        c = c >= Si ? 2 * Si - 2 - c : c;
        cc[i] = c;
    }
    float4 acc = make_float4(0.f, 0.f, 0.f, 0.f);
    #pragma unroll
    for (int i = 0; i < 4; i++) {
        #pragma unroll
        for (int j = 0; j < 4; j++) {
            float w = kk[i] * kk[j];
            float4 v = __ldg(src + rr[i] + cc[j]);
            acc.x += w * v.x; acc.y += w * v.y; acc.z += w * v.z;
        }
    }
    return acc;
}

// ---------------------------------------------------------------------------
// Kernels 3-5: flat downsample stages, one thread per output pixel,
// per-batch early exit (level flag decides whether the stage is needed).
// ---------------------------------------------------------------------------
__global__ void down0_kernel() {                       // img4 -> pyr1 (lev>0)
    int idx = blockIdx.x * blockDim.x + threadIdx.x;   // n*16384 + oh*128 + ow
    int n = idx >> 14;
    if (g_bp[n].lev <= 0.f) return;
    g_pyr14[idx] = down_tap<256>(g_img4 + (size_t)n * 65536,
                                 (idx >> 7) & 127, idx & 127);
}

__global__ void down1_kernel() {                       // pyr1 -> pyr2 (lev>1)
    int idx = blockIdx.x * blockDim.x + threadIdx.x;   // n*4096 + oh*64 + ow
    int n = idx >> 12;
    if (g_bp[n].lev <= 1.f) return;
    g_pyr24[idx] = down_tap<128>(g_pyr14 + (size_t)n * 16384,
                                 (idx >> 6) & 63, idx & 63);
}

__global__ void down2_kernel() {                       // pyr2 -> pyr3 (lev>2)
    int idx = blockIdx.x * blockDim.x + threadIdx.x;   // n*1024 + oh*32 + ow
    int n = idx >> 10;
    if (g_bp[n].lev <= 2.f) return;
    g_pyr34[idx] = down_tap<64>(g_pyr24 + (size_t)n * 4096,
                                (idx >> 5) & 31, idx & 31);
}

// ---------------------------------------------------------------------------
// Bilinear sample (border clamp) from an HWC4 plane. One float4 per tap.
// ---------------------------------------------------------------------------
__device__ __forceinline__ void sample4(const float4* __restrict__ base, int S,
                                        float gx, float gy, float wgt,
                                        float* acc) {
    float x = fmaf(gx + 1.f, 0.5f * (float)S, -0.5f);
    float y = fmaf(gy + 1.f, 0.5f * (float)S, -0.5f);
    float xf = floorf(x), yf = floorf(y);
    float tx = x - xf, ty = y - yf;
    int x0 = (int)xf, y0 = (int)yf;
    int x0c = min(max(x0, 0), S - 1);
    int x1c = min(max(x0 + 1, 0), S - 1);
    int y0c = min(max(y0, 0), S - 1);
    int y1c = min(max(y0 + 1, 0), S - 1);
    float w00 = (1.f - tx) * (1.f - ty) * wgt;
    float w01 = tx * (1.f - ty) * wgt;
    float w10 = (1.f - tx) * ty * wgt;
    float w11 = tx * ty * wgt;
    const float4* r0 = base + y0c * S;
    const float4* r1 = base + y1c * S;
    float4 v00 = __ldg(r0 + x0c);
    float4 v01 = __ldg(r0 + x1c);
    float4 v10 = __ldg(r1 + x0c);
    float4 v11 = __ldg(r1 + x1c);
    acc[0] += v00.x * w00 + v01.x * w01 + v10.x * w10 + v11.x * w11;
    acc[1] += v00.y * w00 + v01.y * w01 + v10.y * w10 + v11.y * w11;
    acc[2] += v00.z * w00 + v01.z * w01 + v10.z * w10 + v11.z * w11;
}

// ---------------------------------------------------------------------------
// Kernel 6: grid gen + mipmap warp. Warp covers an 8x8 pixel tile
// (blockDim 8x16, 2 px per thread vertically) to keep rotated gather
// footprints compact in L1.
// ---------------------------------------------------------------------------
__global__ void warp_kernel(float* __restrict__ out,
                            float* __restrict__ grid_out) {
    int n  = blockIdx.z;
    int w  = blockIdx.x * 8 + threadIdx.x;
    int h0 = blockIdx.y * 32 + threadIdx.y * 2;

    BParam bp = g_bp[n];

    float wc  = ((float)w + 0.5f) * (2.f / (float)WW) - 1.f;
    float hc0 = ((float)h0 + 0.5f) * (2.f / (float)HH) - 1.f;
    float dgx = bp.m01 * (2.f / (float)HH);          // per +1 in h
    float dgy = bp.m11 * (2.f / (float)HH);
    float gx0 = bp.m00 * wc + bp.m01 * hc0 + bp.m02;
    float gy0 = bp.m10 * wc + bp.m11 * hc0 + bp.m12;
    float gx1 = gx0 + dgx;
    float gy1 = gy0 + dgy;

    {   // grid stores: [n][h][w][2], evict-first (write-once)
        float* gp = grid_out + ((size_t)n * 65536 + (size_t)h0 * 256 + w) * 2;
        __stcs(reinterpret_cast<float2*>(gp),       make_float2(gx0, gy0));
        __stcs(reinterpret_cast<float2*>(gp + 512), make_float2(gx1, gy1));
    }

    int l0 = bp.l0;
    float w1 = bp.w1;
    float wgt0 = 1.f - w1;

    const float4* b0; int s0;
    if (l0 == 0)      { b0 = g_img4  + (size_t)n * 65536; s0 = 256; }
    else if (l0 == 1) { b0 = g_pyr14 + (size_t)n * 16384; s0 = 128; }
    else              { b0 = g_pyr24 + (size_t)n * 4096;  s0 = 64;  }

    const float4* b1 = nullptr; int s1 = 0;
    if (w1 > 0.f) {
        if (l0 == 0)      { b1 = g_pyr14 + (size_t)n * 16384; s1 = 128; }
        else if (l0 == 1) { b1 = g_pyr24 + (size_t)n * 4096;  s1 = 64;  }
        else              { b1 = g_pyr34 + (size_t)n * 1024;  s1 = 32;  }
    }

    float a0[3] = {0.f, 0.f, 0.f};
    float a1[3] = {0.f, 0.f, 0.f};
    sample4(b0, s0, gx0, gy0, wgt0, a0);
    sample4(b0, s0, gx1, gy1, wgt0, a1);
    if (b1) {
        sample4(b1, s1, gx0, gy0, w1, a0);
        sample4(b1, s1, gx1, gy1, w1, a1);
    }

    float* o = out + (size_t)n * 3 * 65536 + (size_t)h0 * 256 + w;
    __stcs(o,              a0[0]);
    __stcs(o + 65536,      a0[1]);
    __stcs(o + 131072,     a0[2]);
    __stcs(o + 256,        a1[0]);
    __stcs(o + 65536+256,  a1[1]);
    __stcs(o + 131072+256, a1[2]);
}

// ---------------------------------------------------------------------------
extern "C" void kernel_launch(void* const* d_in, const int* in_sizes, int n_in,
                              void* d_out, int out_size) {
    const float* img  = (const float*)d_in[0];
    const float* feat = (const float*)d_in[1];
    const float* lw   = (const float*)d_in[2];
    const float* lb   = (const float*)d_in[3];

    float* base   = (float*)d_out;
    float* out_p  = base;                                   // N*C*H*W
    float* grid_p = base + (size_t)NB * CCH * HH * WW;
    float* mat_p  = grid_p + (size_t)NB * HH * WW * 2;
    float* aff_p  = mat_p + NB * 6;

    params_kernel<<<NB, 128>>>(feat, lw, lb, mat_p, aff_p);
    hwc_kernel<<<NB * 65536 / 2 / 256, 256>>>(img);
    down0_kernel<<<NB * 16384 / 256, 256>>>();
    down1_kernel<<<NB * 4096 / 256, 256>>>();
    down2_kernel<<<NB * 1024 / 256, 256>>>();

    dim3 blk(8, 16);
    dim3 grd(WW / 8, HH / 32, NB);
    warp_kernel<<<grd, blk>>>(out_p, grid_p);
}